// round 12
// baseline (speedup 1.0000x reference)
#include <cuda_runtime.h>
#include <cuda_fp16.h>

// ---------------- problem constants ----------------
#define BATCH 128
#define CCH   3
#define IMH   224
#define IMW   224
#define GG    32
#define HGI   1024
#define HLI   256
#define DIN   9216
#define NOUT  1280

// ---------------- GEMM (mma.sync fp16) config ----------------
#define NT    64
#define KSTG  32
#define GT    256
#define KS1   18
#define KSLICE1 (DIN / KS1)    // 512
#define NCH1  (KSLICE1 / KSTG) // 16
#define KS2   14               // w3: 10 slices of {4,4,3,3,3,3,3,3,3,3}; w4: 4 of 2

// gemm1 launch: 288 gemm CTAs + 88 mask CTAs
#define G1_GEMM 288
#define G1_MASK 88
#define G1_BLKS (G1_GEMM + G1_MASK)

// SMEM stage layout (fp16, row stride 40 elems = 80 bytes)
#define RS      80
#define OFF_A   0
#define OFF_W   10240              // 128 rows * 80
#define STG_BYTES 15360            // (128 + 64) * 80
#define SMEM_DYN (2 * STG_BYTES)   // 30720 -> 2 CTAs/SM

#define PRO_SMEM 65536             // 128x128 floats for scale-2 staging

// ---------------- scratch (activations in fp16) ----------------
__device__ __half g_phih [BATCH * DIN];
__device__ float  g_part1[KS1 * BATCH * HGI];
__device__ __half g_s1h  [BATCH * HGI];
__device__ __half g_louth[BATCH * HLI];
__device__ float  g_part2[KS2 * BATCH * NOUT];

// ---------------- PTX helpers ----------------
__device__ __forceinline__ unsigned smem_u32(const void* p) {
    unsigned a;
    asm("{ .reg .u64 t; cvta.to.shared.u64 t, %1; cvt.u32.u64 %0, t; }" : "=r"(a) : "l"(p));
    return a;
}
__device__ __forceinline__ void ldsm_x4(unsigned& r0, unsigned& r1, unsigned& r2,
                                        unsigned& r3, unsigned addr) {
    asm volatile("ldmatrix.sync.aligned.m8n8.x4.shared.b16 {%0,%1,%2,%3}, [%4];"
                 : "=r"(r0), "=r"(r1), "=r"(r2), "=r"(r3) : "r"(addr));
}
__device__ __forceinline__ void mma_f16(float* c, const unsigned* a, const unsigned* b) {
    asm volatile("mma.sync.aligned.m16n8k16.row.col.f32.f16.f16.f32 "
                 "{%0,%1,%2,%3}, {%4,%5,%6,%7}, {%8,%9}, {%0,%1,%2,%3};"
                 : "+f"(c[0]), "+f"(c[1]), "+f"(c[2]), "+f"(c[3])
                 : "r"(a[0]), "r"(a[1]), "r"(a[2]), "r"(a[3]), "r"(b[0]), "r"(b[1]));
}
__device__ __forceinline__ uint2 cvt4h(float4 v) {
    __half2 h0 = __floats2half2_rn(v.x, v.y);
    __half2 h1 = __floats2half2_rn(v.z, v.w);
    return make_uint2(*(unsigned*)&h0, *(unsigned*)&h1);
}

// ---------------- split-K fp16 mma.sync GEMM body (A fp16, W fp32) ----------------
__device__ __forceinline__ void gemm_body(const __half* __restrict__ A, int ldA,
                                          const float* __restrict__ W, int ldW,
                                          float* __restrict__ outP, int ldOut,
                                          int bn, int kbeg, int nch) {
    extern __shared__ char smem[];
    const unsigned sb = smem_u32(smem);
    const int tid  = threadIdx.x;
    const int wid  = tid >> 5;
    const int lane = tid & 31;
    const int wm = (wid & 3) * 32;
    const int wn = (wid >> 2) * 32;

    uint2  pa[4];
    float4 pw[2];

    auto ldg_stage = [&](int c) {
        const __half* Ab = A + kbeg + c * KSTG;
#pragma unroll
        for (int j = 0; j < 4; j++) {
            int f4 = j * 256 + tid;
            pa[j] = *(const uint2*)(Ab + (size_t)(f4 >> 3) * ldA + (f4 & 7) * 4);
        }
        const float* Wb = W + (size_t)bn * ldW + kbeg + c * KSTG;
#pragma unroll
        for (int j = 0; j < 2; j++) {
            int f4 = j * 256 + tid;
            pw[j] = *(const float4*)(Wb + (size_t)(f4 >> 3) * ldW + (f4 & 7) * 4);
        }
    };

    auto sts_stage = [&](int s) {
        char* st = smem + s * STG_BYTES;
#pragma unroll
        for (int j = 0; j < 4; j++) {
            int f4 = j * 256 + tid;
            int off = (f4 >> 3) * RS + (f4 & 7) * 8;
            *(uint2*)(st + OFF_A + off) = pa[j];
        }
#pragma unroll
        for (int j = 0; j < 2; j++) {
            int f4 = j * 256 + tid;
            int off = (f4 >> 3) * RS + (f4 & 7) * 8;
            *(uint2*)(st + OFF_W + off) = cvt4h(pw[j]);
        }
    };

    float acc[2][4][4];
#pragma unroll
    for (int i = 0; i < 2; i++)
#pragma unroll
        for (int j = 0; j < 4; j++)
#pragma unroll
            for (int k = 0; k < 4; k++) acc[i][j][k] = 0.0f;

    ldg_stage(0);
    sts_stage(0);
    if (nch > 1) ldg_stage(1);
    __syncthreads();

    for (int c = 0; c < nch; c++) {
        const unsigned base = sb + (unsigned)(c & 1) * STG_BYTES;
#pragma unroll
        for (int kk = 0; kk < KSTG; kk += 16) {
            unsigned af[2][4], bf[4][2];
#pragma unroll
            for (int mb = 0; mb < 2; mb++) {
                unsigned r = wm + mb * 16 + (lane & 15);
                unsigned ko = kk + ((lane & 16) ? 8 : 0);
                unsigned ad = base + r * RS + ko * 2;
                ldsm_x4(af[mb][0], af[mb][1], af[mb][2], af[mb][3], ad + OFF_A);
            }
#pragma unroll
            for (int p = 0; p < 2; p++) {
                unsigned m = lane >> 3;
                unsigned r = wn + p * 16 + ((m >= 2) ? 8 : 0) + (lane & 7);
                unsigned ko = kk + ((m & 1) ? 8 : 0);
                unsigned ad = base + r * RS + ko * 2;
                ldsm_x4(bf[p * 2][0], bf[p * 2][1], bf[p * 2 + 1][0], bf[p * 2 + 1][1],
                        ad + OFF_W);
            }
#pragma unroll
            for (int mb = 0; mb < 2; mb++)
#pragma unroll
                for (int nb = 0; nb < 4; nb++)
                    mma_f16(acc[mb][nb], af[mb], bf[nb]);
        }
        if (c + 1 < nch) {
            sts_stage((c + 1) & 1);
            if (c + 2 < nch) ldg_stage(c + 2);
            __syncthreads();
        }
    }

#pragma unroll
    for (int mb = 0; mb < 2; mb++) {
        const int row = wm + mb * 16 + (lane >> 2);
#pragma unroll
        for (int nb = 0; nb < 4; nb++) {
            const int col = bn + wn + nb * 8 + (lane & 3) * 2;
            float* o = outP + (size_t)row * ldOut + col;
            *(float2*)o = make_float2(acc[mb][nb][0], acc[mb][nb][1]);
            *(float2*)(o + 8 * (size_t)ldOut) = make_float2(acc[mb][nb][2], acc[mb][nb][3]);
        }
    }
}

// ---------------- glimpse helpers ----------------
__device__ __forceinline__ int start_idx(float lv) {
    return (int)(0.5f * ((lv + 1.0f) * 224.0f));
}

__device__ __forceinline__ void mask_task(const float* __restrict__ l,
                                          float* __restrict__ om, int t) {
    const int b = t / 49;
    const int q = (t - b * 49) * 256 + threadIdx.x;
    const int sx = start_idx(l[b * 2 + 0]);
    const int sy = start_idx(l[b * 2 + 1]);
    const int r  = q / 56;
    const int c0 = (q - r * 56) * 4;
    const bool iny = (r >= sy - 64) && (r < sy + 64);
    float4 v;
    v.x = (iny && c0 + 0 >= sx - 64 && c0 + 0 < sx + 64) ? 1.0f : 0.0f;
    v.y = (iny && c0 + 1 >= sx - 64 && c0 + 1 < sx + 64) ? 1.0f : 0.0f;
    v.z = (iny && c0 + 2 >= sx - 64 && c0 + 2 < sx + 64) ? 1.0f : 0.0f;
    v.w = (iny && c0 + 3 >= sx - 64 && c0 + 3 < sx + 64) ? 1.0f : 0.0f;
    ((float4*)(om + (size_t)b * IMH * IMW))[q] = v;
}

// ---------------- prologue: extract (smem-staged) + lout ----------------
#define PRO_BLKS 1280

// scale 0: direct (always in-bounds, coalesced 1 load/elem)
__device__ __forceinline__ void extract_s0(const float* __restrict__ x,
                                           int sx, int sy, int b, int c) {
    const float* xc = x + ((size_t)b * CCH + c) * IMH * IMW;
    __half* dst = g_phih + (size_t)b * DIN + c * GG * GG;
#pragma unroll
    for (int u = 0; u < 4; u++) {
        const int idx = u * 256 + threadIdx.x;    // < 1024
        const int col = idx & 31;
        const int r   = idx >> 5;
        dst[idx] = __float2half(xc[(size_t)(sy - 16 + r) * IMW + (sx - 16 + col)]);
    }
}

// scales 1,2: stage crop in smem (zero-padded), pool with vector reads
template <int SCALE>
__device__ __forceinline__ void extract_sm(const float* __restrict__ x,
                                           int sx, int sy, int b, int c,
                                           float* __restrict__ sm) {
    constexpr int F    = 1 << SCALE;
    constexpr int PAD  = (GG << SCALE) >> 1;
    constexpr int SIZE = GG * F;                 // 64 or 128
    const int row0 = sy - PAD;
    const int col0 = sx - PAD;
    const float* xc = x + ((size_t)b * CCH + c) * IMH * IMW;

    for (int idx = threadIdx.x; idx < SIZE * SIZE; idx += 256) {
        const int r  = idx / SIZE;
        const int cc = idx - r * SIZE;
        const int gr = row0 + r;
        const int gc = col0 + cc;
        float v = 0.0f;
        if (gr >= 0 && gr < IMH && gc >= 0 && gc < IMW)
            v = xc[(size_t)gr * IMW + gc];
        sm[idx] = v;
    }
    __syncthreads();

    const float invf = 1.0f / (float)(F * F);
    __half* dst = g_phih + (size_t)b * DIN + (SCALE * CCH + c) * GG * GG;
#pragma unroll
    for (int u = 0; u < 4; u++) {
        const int o   = u * 256 + threadIdx.x;   // < 1024
        const int col = o & 31;
        const int r   = o >> 5;
        float s = 0.0f;
        if (SCALE == 2) {
#pragma unroll
            for (int dy = 0; dy < 4; dy++) {
                float4 v = ((const float4*)(sm + (r * 4 + dy) * SIZE))[col];
                s += v.x + v.y + v.z + v.w;
            }
        } else {
#pragma unroll
            for (int dy = 0; dy < 2; dy++) {
                float2 v = ((const float2*)(sm + (r * 2 + dy) * SIZE))[col];
                s += v.x + v.y;
            }
        }
        dst[r * GG + col] = __float2half(s * invf);
    }
}

__global__ void prologue_kernel(const float* __restrict__ x,
                                const float* __restrict__ l,
                                const float* __restrict__ w2,
                                const float* __restrict__ b2) {
    extern __shared__ float psm[];
    const int t = blockIdx.x;
    if (t < 1152) {
        const int b  = t & 127;
        const int sc = t >> 7;          // 0..8
        const int c  = sc % 3;
        const int sx = start_idx(l[b * 2 + 0]);
        const int sy = start_idx(l[b * 2 + 1]);
        switch (sc / 3) {
            case 0: extract_s0(x, sx, sy, b, c); break;
            case 1: extract_sm<1>(x, sx, sy, b, c, psm); break;
            default: extract_sm<2>(x, sx, sy, b, c, psm); break;
        }
    } else {
        const int i = (t - 1152) * 256 + threadIdx.x;
        const int m = i >> 8;
        const int j = i & 255;
        float v = fmaf(l[m * 2 + 0], w2[j * 2 + 0],
                  fmaf(l[m * 2 + 1], w2[j * 2 + 1], b2[j]));
        g_louth[i] = __float2half(fmaxf(v, 0.0f));
    }
}

// ---------------- gemm1 (+ mask tail CTAs) ----------------
__global__ void __launch_bounds__(GT, 2) gemm1_mm(const float* __restrict__ w1,
                                                  const float* __restrict__ l,
                                                  float* __restrict__ om) {
    const int cta = blockIdx.x;
    if (cta < G1_GEMM) {
        const int bn = (cta & 15) * NT;
        const int ks = cta >> 4;
        gemm_body(g_phih, DIN, w1, DIN,
                  g_part1 + (size_t)ks * BATCH * HGI, HGI,
                  bn, ks * KSLICE1, NCH1);
    } else {
        for (int t = cta - G1_GEMM; t < BATCH * 49; t += G1_MASK)
            mask_task(l, om, t);
    }
}

// ---------------- gemm2: 280 CTAs, 14-way split-K ----------------
__constant__ int c_kb2 [KS2] = {0, 4, 8, 11, 14, 17, 20, 23, 26, 29, 0, 2, 4, 6};
__constant__ int c_nch2[KS2] = {4, 4, 3, 3, 3, 3, 3, 3, 3, 3, 2, 2, 2, 2};

__global__ void __launch_bounds__(GT, 2) gemm2_mm(const float* __restrict__ w3,
                                                  const float* __restrict__ w4) {
    const int cta = blockIdx.x;          // < 280
    const int bn = (cta % 20) * NT;
    const int z  = cta / 20;
    const __half* A; const float* W; int ld;
    if (z < 10) { A = g_s1h;   W = w3; ld = HGI; }
    else        { A = g_louth; W = w4; ld = HLI; }
    gemm_body(A, ld, W, ld,
              g_part2 + (size_t)z * BATCH * NOUT, NOUT,
              bn, c_kb2[z] * KSTG, c_nch2[z]);
}

// ---------------- reductions ----------------
__global__ void reduce1_kernel(const float* __restrict__ b1) {
    const int i4 = blockIdx.x * blockDim.x + threadIdx.x;  // < 32768
    float4 s = ((const float4*)g_part1)[i4];
#pragma unroll
    for (int p = 1; p < KS1; p++) {
        float4 v = ((const float4*)(g_part1 + (size_t)p * BATCH * HGI))[i4];
        s.x += v.x; s.y += v.y; s.z += v.z; s.w += v.w;
    }
    float4 bb = ((const float4*)b1)[i4 & 255];
    s.x = fmaxf(s.x + bb.x, 0.0f); s.y = fmaxf(s.y + bb.y, 0.0f);
    s.z = fmaxf(s.z + bb.z, 0.0f); s.w = fmaxf(s.w + bb.w, 0.0f);
    ((uint2*)g_s1h)[i4] = cvt4h(s);
}

__global__ void reduce2_kernel(const float* __restrict__ b3,
                               const float* __restrict__ b4,
                               float* __restrict__ out) {
    const int i4 = blockIdx.x * blockDim.x + threadIdx.x;  // < 40960
    float4 s = ((const float4*)g_part2)[i4];
#pragma unroll
    for (int p = 1; p < KS2; p++) {
        float4 v = ((const float4*)(g_part2 + (size_t)p * BATCH * NOUT))[i4];
        s.x += v.x; s.y += v.y; s.z += v.z; s.w += v.w;
    }
    const int n4 = i4 % (NOUT / 4);
    float4 t3 = ((const float4*)b3)[n4];
    float4 t4 = ((const float4*)b4)[n4];
    s.x = fmaxf(s.x + t3.x + t4.x, 0.0f); s.y = fmaxf(s.y + t3.y + t4.y, 0.0f);
    s.z = fmaxf(s.z + t3.z + t4.z, 0.0f); s.w = fmaxf(s.w + t3.w + t4.w, 0.0f);
    ((float4*)out)[i4] = s;
}

// ---------------- launch ----------------
extern "C" void kernel_launch(void* const* d_in, const int* in_sizes, int n_in,
                              void* d_out, int out_size) {
    const float* x  = (const float*)d_in[0];
    const float* l  = (const float*)d_in[1];
    const float* w1 = (const float*)d_in[2];
    const float* b1 = (const float*)d_in[3];
    const float* w2 = (const float*)d_in[4];
    const float* b2 = (const float*)d_in[5];
    const float* w3 = (const float*)d_in[6];
    const float* b3 = (const float*)d_in[7];
    const float* w4 = (const float*)d_in[8];
    const float* b4 = (const float*)d_in[9];
    float* out = (float*)d_out;

    cudaFuncSetAttribute(prologue_kernel, cudaFuncAttributeMaxDynamicSharedMemorySize, PRO_SMEM);
    cudaFuncSetAttribute(gemm1_mm, cudaFuncAttributeMaxDynamicSharedMemorySize, SMEM_DYN);
    cudaFuncSetAttribute(gemm2_mm, cudaFuncAttributeMaxDynamicSharedMemorySize, SMEM_DYN);

    prologue_kernel<<<PRO_BLKS, 256, PRO_SMEM>>>(x, l, w2, b2);
    gemm1_mm<<<G1_BLKS, GT, SMEM_DYN>>>(w1, l, out + BATCH * NOUT);
    reduce1_kernel<<<(BATCH * HGI / 4) / 256, 256>>>(b1);
    gemm2_mm<<<20 * KS2, GT, SMEM_DYN>>>(w3, w4);
    reduce2_kernel<<<(BATCH * NOUT / 4) / 256, 256>>>(b3, b4, out);
}

// round 15
// speedup vs baseline: 1.1323x; 1.1323x over previous
#include <cuda_runtime.h>
#include <cuda_fp16.h>

// ---------------- problem constants ----------------
#define BATCH 128
#define CCH   3
#define IMH   224
#define IMW   224
#define GG    32
#define HGI   1024
#define HLI   256
#define DIN   9216
#define NOUT  1280

// ---------------- GEMM (mma.sync fp16) config ----------------
#define NT    64
#define KSTG  32
#define GT    256
#define KS1   18
#define KSLICE1 (DIN / KS1)    // 512
#define NCH1  (KSLICE1 / KSTG) // 16
#define KS2   14               // w3: {4,4,3,3,3,3,3,3,3,3}; w4: {2,2,2,2}

// gemm1 launch: 288 gemm CTAs + 88 mask CTAs
#define G1_GEMM 288
#define G1_MASK 88
#define G1_BLKS (G1_GEMM + G1_MASK)

// SMEM stage layout (fp16, row stride 40 elems = 80 bytes)
#define RS      80
#define OFF_A   0
#define OFF_W   10240              // 128 rows * 80
#define STG_BYTES 15360            // (128 + 64) * 80
#define SMEM_DYN (2 * STG_BYTES)   // 30720 -> 2 CTAs/SM

// ---------------- scratch (activations in fp16) ----------------
__device__ __half g_phih [BATCH * DIN];
__device__ float  g_part1[KS1 * BATCH * HGI];
__device__ __half g_s1h  [BATCH * HGI];
__device__ __half g_louth[BATCH * HLI];
__device__ float  g_part2[KS2 * BATCH * NOUT];

// ---------------- PTX helpers ----------------
__device__ __forceinline__ unsigned smem_u32(const void* p) {
    unsigned a;
    asm("{ .reg .u64 t; cvta.to.shared.u64 t, %1; cvt.u32.u64 %0, t; }" : "=r"(a) : "l"(p));
    return a;
}
__device__ __forceinline__ void ldsm_x4(unsigned& r0, unsigned& r1, unsigned& r2,
                                        unsigned& r3, unsigned addr) {
    asm volatile("ldmatrix.sync.aligned.m8n8.x4.shared.b16 {%0,%1,%2,%3}, [%4];"
                 : "=r"(r0), "=r"(r1), "=r"(r2), "=r"(r3) : "r"(addr));
}
__device__ __forceinline__ void mma_f16(float* c, const unsigned* a, const unsigned* b) {
    asm volatile("mma.sync.aligned.m16n8k16.row.col.f32.f16.f16.f32 "
                 "{%0,%1,%2,%3}, {%4,%5,%6,%7}, {%8,%9}, {%0,%1,%2,%3};"
                 : "+f"(c[0]), "+f"(c[1]), "+f"(c[2]), "+f"(c[3])
                 : "r"(a[0]), "r"(a[1]), "r"(a[2]), "r"(a[3]), "r"(b[0]), "r"(b[1]));
}
__device__ __forceinline__ uint2 cvt4h(float4 v) {
    __half2 h0 = __floats2half2_rn(v.x, v.y);
    __half2 h1 = __floats2half2_rn(v.z, v.w);
    return make_uint2(*(unsigned*)&h0, *(unsigned*)&h1);
}

// ---------------- split-K fp16 mma.sync GEMM body (A fp16, W fp32) ----------------
__device__ __forceinline__ void gemm_body(const __half* __restrict__ A, int ldA,
                                          const float* __restrict__ W, int ldW,
                                          float* __restrict__ outP, int ldOut,
                                          int bn, int kbeg, int nch) {
    extern __shared__ char smem[];
    const unsigned sb = smem_u32(smem);
    const int tid  = threadIdx.x;
    const int wid  = tid >> 5;
    const int lane = tid & 31;
    const int wm = (wid & 3) * 32;
    const int wn = (wid >> 2) * 32;

    uint2  pa[4];
    float4 pw[2];

    auto ldg_stage = [&](int c) {
        const __half* Ab = A + kbeg + c * KSTG;
#pragma unroll
        for (int j = 0; j < 4; j++) {
            int f4 = j * 256 + tid;
            pa[j] = *(const uint2*)(Ab + (size_t)(f4 >> 3) * ldA + (f4 & 7) * 4);
        }
        const float* Wb = W + (size_t)bn * ldW + kbeg + c * KSTG;
#pragma unroll
        for (int j = 0; j < 2; j++) {
            int f4 = j * 256 + tid;
            pw[j] = *(const float4*)(Wb + (size_t)(f4 >> 3) * ldW + (f4 & 7) * 4);
        }
    };

    auto sts_stage = [&](int s) {
        char* st = smem + s * STG_BYTES;
#pragma unroll
        for (int j = 0; j < 4; j++) {
            int f4 = j * 256 + tid;
            int off = (f4 >> 3) * RS + (f4 & 7) * 8;
            *(uint2*)(st + OFF_A + off) = pa[j];
        }
#pragma unroll
        for (int j = 0; j < 2; j++) {
            int f4 = j * 256 + tid;
            int off = (f4 >> 3) * RS + (f4 & 7) * 8;
            *(uint2*)(st + OFF_W + off) = cvt4h(pw[j]);
        }
    };

    float acc[2][4][4];
#pragma unroll
    for (int i = 0; i < 2; i++)
#pragma unroll
        for (int j = 0; j < 4; j++)
#pragma unroll
            for (int k = 0; k < 4; k++) acc[i][j][k] = 0.0f;

    ldg_stage(0);
    sts_stage(0);
    if (nch > 1) ldg_stage(1);
    __syncthreads();

    for (int c = 0; c < nch; c++) {
        const unsigned base = sb + (unsigned)(c & 1) * STG_BYTES;
#pragma unroll
        for (int kk = 0; kk < KSTG; kk += 16) {
            unsigned af[2][4], bf[4][2];
#pragma unroll
            for (int mb = 0; mb < 2; mb++) {
                unsigned r = wm + mb * 16 + (lane & 15);
                unsigned ko = kk + ((lane & 16) ? 8 : 0);
                unsigned ad = base + r * RS + ko * 2;
                ldsm_x4(af[mb][0], af[mb][1], af[mb][2], af[mb][3], ad + OFF_A);
            }
#pragma unroll
            for (int p = 0; p < 2; p++) {
                unsigned m = lane >> 3;
                unsigned r = wn + p * 16 + ((m >= 2) ? 8 : 0) + (lane & 7);
                unsigned ko = kk + ((m & 1) ? 8 : 0);
                unsigned ad = base + r * RS + ko * 2;
                ldsm_x4(bf[p * 2][0], bf[p * 2][1], bf[p * 2 + 1][0], bf[p * 2 + 1][1],
                        ad + OFF_W);
            }
#pragma unroll
            for (int mb = 0; mb < 2; mb++)
#pragma unroll
                for (int nb = 0; nb < 4; nb++)
                    mma_f16(acc[mb][nb], af[mb], bf[nb]);
        }
        if (c + 1 < nch) {
            sts_stage((c + 1) & 1);
            if (c + 2 < nch) ldg_stage(c + 2);
            __syncthreads();
        }
    }

#pragma unroll
    for (int mb = 0; mb < 2; mb++) {
        const int row = wm + mb * 16 + (lane >> 2);
#pragma unroll
        for (int nb = 0; nb < 4; nb++) {
            const int col = bn + wn + nb * 8 + (lane & 3) * 2;
            float* o = outP + (size_t)row * ldOut + col;
            *(float2*)o = make_float2(acc[mb][nb][0], acc[mb][nb][1]);
            *(float2*)(o + 8 * (size_t)ldOut) = make_float2(acc[mb][nb][2], acc[mb][nb][3]);
        }
    }
}

// ---------------- glimpse helpers ----------------
__device__ __forceinline__ int start_idx(float lv) {
    return (int)(0.5f * ((lv + 1.0f) * 224.0f));
}

__device__ __forceinline__ void mask_task(const float* __restrict__ l,
                                          float* __restrict__ om, int t) {
    const int b = t / 49;
    const int q = (t - b * 49) * 256 + threadIdx.x;
    const int sx = start_idx(l[b * 2 + 0]);
    const int sy = start_idx(l[b * 2 + 1]);
    const int r  = q / 56;
    const int c0 = (q - r * 56) * 4;
    const bool iny = (r >= sy - 64) && (r < sy + 64);
    float4 v;
    v.x = (iny && c0 + 0 >= sx - 64 && c0 + 0 < sx + 64) ? 1.0f : 0.0f;
    v.y = (iny && c0 + 1 >= sx - 64 && c0 + 1 < sx + 64) ? 1.0f : 0.0f;
    v.z = (iny && c0 + 2 >= sx - 64 && c0 + 2 < sx + 64) ? 1.0f : 0.0f;
    v.w = (iny && c0 + 3 >= sx - 64 && c0 + 3 < sx + 64) ? 1.0f : 0.0f;
    ((float4*)(om + (size_t)b * IMH * IMW))[q] = v;
}

// ---------------- prologue: direct extract per (b, scale, ch) + lout ----------------
#define PRO_BLKS 1280

// scale 0: always in-bounds (start in [56,168], pad 16 -> rows [40,184))
__device__ __forceinline__ void extract_s0(const float* __restrict__ x,
                                           int sx, int sy, int b, int c) {
    const float* xc = x + ((size_t)b * CCH + c) * IMH * IMW;
    __half* dst = g_phih + (size_t)b * DIN + c * GG * GG;
#pragma unroll
    for (int u = 0; u < 4; u++) {
        const int idx = u * 256 + threadIdx.x;    // < 1024
        const int col = idx & 31;
        const int r   = idx >> 5;
        dst[idx] = __float2half(xc[(size_t)(sy - 16 + r) * IMW + (sx - 16 + col)]);
    }
}

template <int SCALE>
__device__ __forceinline__ void extract_ch(const float* __restrict__ x,
                                           int sx, int sy, int b, int c) {
    constexpr int F   = 1 << SCALE;
    constexpr int PAD = (GG << SCALE) >> 1;
    const float* xc = x + ((size_t)b * CCH + c) * IMH * IMW;
    const float invf = 1.0f / (float)(F * F);
    __half* dst = g_phih + (size_t)b * DIN + (SCALE * CCH + c) * GG * GG;

#pragma unroll
    for (int u = 0; u < 4; u++) {
        const int idx = u * 256 + threadIdx.x;   // < 1024
        const int col = idx & 31;
        const int r   = idx >> 5;
        const int row0 = sy - PAD + r * F;
        const int col0 = sx - PAD + col * F;
        float s = 0.0f;
#pragma unroll
        for (int dy = 0; dy < F; dy++) {
            const int rr = row0 + dy;
            if (rr < 0 || rr >= IMH) continue;
            const float* xr = xc + (size_t)rr * IMW;
#pragma unroll
            for (int dx = 0; dx < F; dx++) {
                const int cc = col0 + dx;
                if (cc >= 0 && cc < IMW) s += xr[cc];
            }
        }
        dst[r * GG + col] = __float2half(s * invf);
    }
}

__global__ void prologue_kernel(const float* __restrict__ x,
                                const float* __restrict__ l,
                                const float* __restrict__ w2,
                                const float* __restrict__ b2) {
    const int t = blockIdx.x;
    if (t < 1152) {
        const int b  = t & 127;
        const int sc = t >> 7;          // 0..8
        const int c  = sc % 3;
        const int sx = start_idx(l[b * 2 + 0]);
        const int sy = start_idx(l[b * 2 + 1]);
        switch (sc / 3) {
            case 0: extract_s0(x, sx, sy, b, c); break;
            case 1: extract_ch<1>(x, sx, sy, b, c); break;
            default: extract_ch<2>(x, sx, sy, b, c); break;
        }
    } else {
        const int i = (t - 1152) * 256 + threadIdx.x;
        const int m = i >> 8;
        const int j = i & 255;
        float v = fmaf(l[m * 2 + 0], w2[j * 2 + 0],
                  fmaf(l[m * 2 + 1], w2[j * 2 + 1], b2[j]));
        g_louth[i] = __float2half(fmaxf(v, 0.0f));
    }
}

// ---------------- gemm1 (+ mask tail CTAs) ----------------
__global__ void __launch_bounds__(GT, 2) gemm1_mm(const float* __restrict__ w1,
                                                  const float* __restrict__ l,
                                                  float* __restrict__ om) {
    const int cta = blockIdx.x;
    if (cta < G1_GEMM) {
        const int bn = (cta & 15) * NT;
        const int ks = cta >> 4;
        gemm_body(g_phih, DIN, w1, DIN,
                  g_part1 + (size_t)ks * BATCH * HGI, HGI,
                  bn, ks * KSLICE1, NCH1);
    } else {
        for (int t = cta - G1_GEMM; t < BATCH * 49; t += G1_MASK)
            mask_task(l, om, t);
    }
}

// ---------------- gemm2: 280 CTAs, 14-way split-K ----------------
__constant__ int c_kb2 [KS2] = {0, 4, 8, 11, 14, 17, 20, 23, 26, 29, 0, 2, 4, 6};
__constant__ int c_nch2[KS2] = {4, 4, 3, 3, 3, 3, 3, 3, 3, 3, 2, 2, 2, 2};

__global__ void __launch_bounds__(GT, 2) gemm2_mm(const float* __restrict__ w3,
                                                  const float* __restrict__ w4) {
    const int cta = blockIdx.x;          // < 280
    const int bn = (cta % 20) * NT;
    const int z  = cta / 20;
    const __half* A; const float* W; int ld;
    if (z < 10) { A = g_s1h;   W = w3; ld = HGI; }
    else        { A = g_louth; W = w4; ld = HLI; }
    gemm_body(A, ld, W, ld,
              g_part2 + (size_t)z * BATCH * NOUT, NOUT,
              bn, c_kb2[z] * KSTG, c_nch2[z]);
}

// ---------------- reductions ----------------
__global__ void reduce1_kernel(const float* __restrict__ b1) {
    const int i4 = blockIdx.x * blockDim.x + threadIdx.x;  // < 32768
    float4 s = ((const float4*)g_part1)[i4];
#pragma unroll
    for (int p = 1; p < KS1; p++) {
        float4 v = ((const float4*)(g_part1 + (size_t)p * BATCH * HGI))[i4];
        s.x += v.x; s.y += v.y; s.z += v.z; s.w += v.w;
    }
    float4 bb = ((const float4*)b1)[i4 & 255];
    s.x = fmaxf(s.x + bb.x, 0.0f); s.y = fmaxf(s.y + bb.y, 0.0f);
    s.z = fmaxf(s.z + bb.z, 0.0f); s.w = fmaxf(s.w + bb.w, 0.0f);
    ((uint2*)g_s1h)[i4] = cvt4h(s);
}

__global__ void reduce2_kernel(const float* __restrict__ b3,
                               const float* __restrict__ b4,
                               float* __restrict__ out) {
    const int i4 = blockIdx.x * blockDim.x + threadIdx.x;  // < 40960
    float4 s = ((const float4*)g_part2)[i4];
#pragma unroll
    for (int p = 1; p < KS2; p++) {
        float4 v = ((const float4*)(g_part2 + (size_t)p * BATCH * NOUT))[i4];
        s.x += v.x; s.y += v.y; s.z += v.z; s.w += v.w;
    }
    const int n4 = i4 % (NOUT / 4);
    float4 t3 = ((const float4*)b3)[n4];
    float4 t4 = ((const float4*)b4)[n4];
    s.x = fmaxf(s.x + t3.x + t4.x, 0.0f); s.y = fmaxf(s.y + t3.y + t4.y, 0.0f);
    s.z = fmaxf(s.z + t3.z + t4.z, 0.0f); s.w = fmaxf(s.w + t3.w + t4.w, 0.0f);
    ((float4*)out)[i4] = s;
}

// ---------------- launch ----------------
extern "C" void kernel_launch(void* const* d_in, const int* in_sizes, int n_in,
                              void* d_out, int out_size) {
    const float* x  = (const float*)d_in[0];
    const float* l  = (const float*)d_in[1];
    const float* w1 = (const float*)d_in[2];
    const float* b1 = (const float*)d_in[3];
    const float* w2 = (const float*)d_in[4];
    const float* b2 = (const float*)d_in[5];
    const float* w3 = (const float*)d_in[6];
    const float* b3 = (const float*)d_in[7];
    const float* w4 = (const float*)d_in[8];
    const float* b4 = (const float*)d_in[9];
    float* out = (float*)d_out;

    cudaFuncSetAttribute(gemm1_mm, cudaFuncAttributeMaxDynamicSharedMemorySize, SMEM_DYN);
    cudaFuncSetAttribute(gemm2_mm, cudaFuncAttributeMaxDynamicSharedMemorySize, SMEM_DYN);

    prologue_kernel<<<PRO_BLKS, 256>>>(x, l, w2, b2);
    gemm1_mm<<<G1_BLKS, GT, SMEM_DYN>>>(w1, l, out + BATCH * NOUT);
    reduce1_kernel<<<(BATCH * HGI / 4) / 256, 256>>>(b1);
    gemm2_mm<<<20 * KS2, GT, SMEM_DYN>>>(w3, w4);
    reduce2_kernel<<<(BATCH * NOUT / 4) / 256, 256>>>(b3, b4, out);
}